// round 9
// baseline (speedup 1.0000x reference)
#include <cuda_runtime.h>
#include <cuda_bf16.h>
#include <cstddef>

// Problem shapes (fixed per reference setup_inputs):
//   idx:    [B, 2, N] f32,  B=16, N = 512*512 = 262144
//   source: [B, 640, 640, 3] f32
//   out:    [B, 512, 512, 3] f32
static constexpr int B_    = 16;
static constexpr int HS    = 640;
static constexpr int WS    = 640;
static constexpr int C_    = 3;
static constexpr int NPIX  = 512 * 512;                  // 262144 per batch
static constexpr long long NTOT = (long long)B_ * NPIX;  // 4,194,304

// L1-wavefront-bound gather (R1/R3 ncu: L1tex is the binding resource).
// Per pixel, the 12 needed bytes start at element s = 3*q (alignment m = s&3
// uniform-random). Scheme:
//   - always:        LDG.128 at f = s & ~3   (16B-aligned, 1 sector, 1 wf)
//   - iff m >= 2:    LDG.64  at f + 4        (predicated; half the lanes)
// => avg 1.5 gather wavefronts/pixel (was 2.0 with 2x LDG.64, 3.0 with 3x LDG.32).
// Reassembly: c_k = w[m+k] from w = {A.x,A.y,A.z,A.w,B.x,B.y} via SELs.
// Bounds: for m>=2 the max touched element is f+5 = s+3 (m=3) with
// s <= 1228794 -> 1228797 < 640*640*3 = 1228800. The m<=1 path touches at
// most f+3 <= s+3 <= 1228799. All in bounds; the f+4 load is predicate-
// guarded so it never issues for m<=1 or invalid pixels.
__global__ void __launch_bounds__(256) nn_gather_kernel(
    const float* __restrict__ idx,
    const float* __restrict__ src,
    float* __restrict__ out)
{
    long long g = (long long)blockIdx.x * blockDim.x + threadIdx.x;
    long long p0 = g * 4;                 // first pixel of this group
    if (p0 >= NTOT) return;

    int b = (int)(p0 / NPIX);
    int n = (int)(p0 - (long long)b * NPIX);   // NPIX % 4 == 0 -> group stays in one batch

    const float* idx_b = idx + (size_t)b * 2 * NPIX;
    float4 rows = *reinterpret_cast<const float4*>(idx_b + n);
    float4 cols = *reinterpret_cast<const float4*>(idx_b + NPIX + n);

    const float* sb = src + (size_t)b * HS * WS * C_;

    float rf[4] = {rows.x, rows.y, rows.z, rows.w};
    float cf[4] = {cols.x, cols.y, cols.z, cols.w};

    float v[12];
#pragma unroll
    for (int i = 0; i < 4; ++i) {
        // trunc(x + 0.5) toward zero, exactly like jnp.trunc(...).astype(int32)
        int ir = (int)(rf[i] + 0.5f);
        int ic = (int)(cf[i] + 0.5f);
        bool valid = (ir >= 0) & (ic >= 0) & (ir < HS) & (ic < WS);
        float c0 = 0.0f, c1 = 0.0f, c2 = 0.0f;
        if (valid) {
            int s = (ir * WS + ic) * C_;       // element index, alignment m = s & 3
            int f = s & ~3;                    // 16B-aligned base
            int m = s & 3;
            float4 A = *reinterpret_cast<const float4*>(sb + f);   // f .. f+3
            float2 Bv = make_float2(0.0f, 0.0f);
            if (m >= 2) {                      // predicated LDG.64, ~half the lanes
                Bv = *reinterpret_cast<const float2*>(sb + f + 4); // f+4, f+5
            }
            // c_k = w[m + k],  w = {A.x, A.y, A.z, A.w, Bv.x, Bv.y}
            bool m1 = (m & 1) != 0;
            bool m2 = (m & 2) != 0;
            // w[m]   : m=0->A.x  1->A.y  2->A.z  3->A.w
            c0 = m2 ? (m1 ? A.w : A.z) : (m1 ? A.y : A.x);
            // w[m+1] : m=0->A.y  1->A.z  2->A.w  3->Bv.x
            c1 = m2 ? (m1 ? Bv.x : A.w) : (m1 ? A.z : A.y);
            // w[m+2] : m=0->A.z  1->A.w  2->Bv.x 3->Bv.y
            c2 = m2 ? (m1 ? Bv.y : Bv.x) : (m1 ? A.w : A.z);
        }
        v[i * 3 + 0] = c0;
        v[i * 3 + 1] = c1;
        v[i * 3 + 2] = c2;
    }

    float4* o = reinterpret_cast<float4*>(out + (size_t)p0 * 3);
    o[0] = make_float4(v[0], v[1], v[2],  v[3]);
    o[1] = make_float4(v[4], v[5], v[6],  v[7]);
    o[2] = make_float4(v[8], v[9], v[10], v[11]);
}

extern "C" void kernel_launch(void* const* d_in, const int* in_sizes, int n_in,
                              void* d_out, int out_size)
{
    const float* idx = (const float*)d_in[0];   // [16, 2, 262144] f32
    const float* src = (const float*)d_in[1];   // [16, 640, 640, 3] f32
    float* out = (float*)d_out;                 // [16, 512, 512, 3] f32

    (void)in_sizes; (void)n_in; (void)out_size;

    const long long n_groups = NTOT / 4;        // 1,048,576
    const int threads = 256;
    const int blocks = (int)((n_groups + threads - 1) / threads);  // 4096
    nn_gather_kernel<<<blocks, threads>>>(idx, src, out);
}